// round 16
// baseline (speedup 1.0000x reference)
#include <cuda_runtime.h>
#include <cuda_fp16.h>
#include <math.h>
#include <stdint.h>

#define NNODES 16384
#define NEDGES 98304
#define NCAND  1024

__device__ __forceinline__ int hidx(int k) {
    int kp = k >> 1, s = kp & 7;
    return ((kp >> 3) << 4) + ((((s & 3) << 1) | (s >> 2)) << 1) + (k & 1);
}

// ---------------- scratch ----------------
__device__ float g_x1[NNODES * 512];
__device__ float g_x2[NNODES * 1024];
__device__ float g_x3[NCAND * 64];
__device__ float g_proj[NNODES * 1024];
__device__ float g_skip[NNODES * 1024];  // L1 skip; L2: zskip[NCAND*64]
__device__ float g_ssrc[NNODES * 8];
__device__ float g_stgt[NNODES * 8];
__device__ float g_alpha[NEDGES * 8];
__device__ int   g_cnt[NNODES];
__device__ int   g_off[NNODES + 1];
__device__ int   g_cur[NNODES];
__device__ int   g_srcs[NEDGES];
__device__ float g_csrc[24];
__device__ float g_ctgt[24];
__device__ float g_c1[8192];
__device__ float g_c2[2048];
__device__ uint32_t g_wtf[1179648];

// ---------------- merged setup kernel 1 ----------------
__device__ void convTP_dev(const float* __restrict__ in, __half* __restrict__ out,
                           int K, int M, int bx, int by, int tid) {
    __shared__ float t[32][33];
    const int k0 = bx * 32, m0 = by * 32;
    const int tx = tid & 31, ty = tid >> 5;
    for (int i = ty; i < 32; i += 8)
        t[i][tx] = in[(size_t)(k0 + i) * M + m0 + tx];
    __syncthreads();
    for (int i = ty; i < 32; i += 8) {
        int m = m0 + i, k = k0 + tx;
        out[(size_t)m * K + hidx(k)] = __float2half_rn(t[tx][i]);
    }
}

// blocks: [0,512) W1 | [512,1024) S1 | [1024,1088) W2 | [1088,1152) zero_cnt
//         [1152,1184) fold1 | [1184,1192) fold2 | [1192] precomp_c
__global__ __launch_bounds__(256)
void setup1_kernel(const float* __restrict__ W1, const float* __restrict__ S1,
                   const float* __restrict__ W2,
                   const float* __restrict__ W0,
                   const float* __restrict__ a_src0, const float* __restrict__ a_tgt0,
                   const float* __restrict__ a_src1, const float* __restrict__ a_tgt1,
                   const float* __restrict__ a_src2, const float* __restrict__ a_tgt2,
                   __half* __restrict__ W1t, __half* __restrict__ S1t,
                   __half* __restrict__ W2t) {
    const int b = blockIdx.x;
    const int tid = threadIdx.x;
    if (b < 512) {
        convTP_dev(W1, W1t, 512, 1024, b & 15, b >> 4, tid);
    } else if (b < 1024) {
        int bb = b - 512;
        convTP_dev(S1, S1t, 512, 1024, bb & 15, bb >> 4, tid);
    } else if (b < 1088) {
        int bb = b - 1024;
        convTP_dev(W2, W2t, 1024, 64, bb & 31, bb >> 5, tid);
    } else if (b < 1152) {
        int i = (b - 1088) * 256 + tid;
        if (i < NNODES) g_cnt[i] = 0;
    } else if (b < 1184) {
        int t = (b - 1152) * 256 + tid;
        int isT = t >= 4096;
        int i = t & 4095;
        int h = i >> 9, k = i & 511;
        const float* a = isT ? a_tgt1 : a_src1;
        float s = 0.f;
#pragma unroll 4
        for (int f = 0; f < 128; f++)
            s += W1[(size_t)k * 1024 + h * 128 + f] * a[h * 128 + f];
        g_c1[isT * 4096 + h * 512 + hidx(k)] = s;
    } else if (b < 1192) {
        int t = (b - 1184) * 256 + tid;
        int isT = t >= 1024;
        int k = t & 1023;
        const float* a = isT ? a_tgt2 : a_src2;
        float s = 0.f;
#pragma unroll 8
        for (int f = 0; f < 64; f++) s += W2[(size_t)k * 64 + f] * a[f];
        g_c2[isT * 1024 + hidx(k)] = s;
    } else {
        if (tid < 48) {
            int isT = tid >= 24;
            int i = isT ? tid - 24 : tid;
            int h = i / 3, d = i % 3;
            const float* a = isT ? a_tgt0 : a_src0;
            float s = 0.f;
            for (int f = 0; f < 64; f++)
                s += W0[d * 512 + h * 64 + f] * a[h * 64 + f];
            (isT ? g_ctgt : g_csrc)[i] = s;
        }
    }
}

// ---------------- merged setup kernel 2: count + l0_scores ----------------
__global__ __launch_bounds__(256)
void setup2_kernel(const int* __restrict__ tgt, const float* __restrict__ fea) {
    const int b = blockIdx.x;
    const int tid = threadIdx.x;
    if (b < 384) {
        int e = b * 256 + tid;
        if (e < NEDGES) atomicAdd(&g_cnt[tgt[e]], 1);
    } else {
        int i = (b - 384) * 256 + tid;
        if (i < NNODES * 8) {
            int n = i >> 3, h = i & 7;
            float f0 = fea[n * 3 + 0], f1 = fea[n * 3 + 1], f2 = fea[n * 3 + 2];
            g_ssrc[i] = f0 * g_csrc[h * 3] + f1 * g_csrc[h * 3 + 1] + f2 * g_csrc[h * 3 + 2];
            g_stgt[i] = f0 * g_ctgt[h * 3] + f1 * g_ctgt[h * 3 + 1] + f2 * g_ctgt[h * 3 + 2];
        }
    }
}

__global__ void scan_kernel() {
    __shared__ int part[1024];
    const int PER = NNODES / 1024;
    int tid = threadIdx.x;
    int base = tid * PER;
    int local[PER];
    int s = 0;
#pragma unroll
    for (int i = 0; i < PER; i++) { local[i] = g_cnt[base + i]; s += local[i]; }
    part[tid] = s;
    __syncthreads();
    for (int d = 1; d < 1024; d <<= 1) {
        int v = (tid >= d) ? part[tid - d] : 0;
        __syncthreads();
        part[tid] += v;
        __syncthreads();
    }
    int run = (tid == 0) ? 0 : part[tid - 1];
#pragma unroll
    for (int i = 0; i < PER; i++) {
        g_off[base + i] = run;
        g_cur[base + i] = run;
        run += local[i];
    }
    if (tid == 1023) g_off[NNODES] = run;
}
__global__ void scatter_kernel(const int* __restrict__ src, const int* __restrict__ tgt) {
    int e = blockIdx.x * blockDim.x + threadIdx.x;
    if (e < NEDGES) {
        int p = atomicAdd(&g_cur[tgt[e]], 1);
        g_srcs[p] = src[e];
    }
}

// ---------------- fused layer 0 agg ----------------
__global__ __launch_bounds__(512)
void agg0_kernel(const float* __restrict__ fea,
                 const float* __restrict__ W0, const float* __restrict__ S0,
                 const float* __restrict__ b0, __half* __restrict__ out) {
    const int n = blockIdx.x;
    const int tid = threadIdx.x;
    const int warp = tid >> 5, lane = tid & 31;
    const int beg = g_off[n], end = g_off[n + 1];

    const float w0 = W0[tid], w1 = W0[512 + tid], w2 = W0[1024 + tid];
    const float s0 = S0[tid], s1 = S0[512 + tid], s2 = S0[1024 + tid];

    __shared__ float mh[8], ivh[8];
    __shared__ float al[32 * 8];
    __shared__ float sf[32 * 3];

    if (warp < 8) {
        const int h = warp;
        const float st = g_stgt[n * 8 + h];
        float m = -1e30f;
        for (int j = beg + lane; j < end; j += 32) {
            float e = g_ssrc[g_srcs[j] * 8 + h] + st;
            e = (e < 0.f) ? 0.2f * e : e;
            m = fmaxf(m, e);
        }
#pragma unroll
        for (int o = 16; o; o >>= 1) m = fmaxf(m, __shfl_xor_sync(0xffffffffu, m, o));
        float ss = 0.f;
        for (int j = beg + lane; j < end; j += 32) {
            float e = g_ssrc[g_srcs[j] * 8 + h] + st;
            e = (e < 0.f) ? 0.2f * e : e;
            ss += expf(e - m);
        }
#pragma unroll
        for (int o = 16; o; o >>= 1) ss += __shfl_xor_sync(0xffffffffu, ss, o);
        if (lane == 0) { mh[h] = m; ivh[h] = 1.f / (ss + 1e-16f); }
    }
    __syncthreads();

    const int myh = tid >> 6;
    float acc = 0.f;
    for (int j0 = beg; j0 < end; j0 += 32) {
        const int nj = min(32, end - j0);
        if (tid < 256) {
            const int l = tid & 31, h = tid >> 5;
            if (l < nj) {
                const int s = g_srcs[j0 + l];
                const float st = g_stgt[n * 8 + h];
                float e = g_ssrc[s * 8 + h] + st;
                e = (e < 0.f) ? 0.2f * e : e;
                al[l * 8 + h] = expf(e - mh[h]) * ivh[h];
                if (h == 0) {
                    sf[l * 3 + 0] = fea[s * 3 + 0];
                    sf[l * 3 + 1] = fea[s * 3 + 1];
                    sf[l * 3 + 2] = fea[s * 3 + 2];
                }
            }
        }
        __syncthreads();
        for (int l = 0; l < nj; l++) {
            const float a = al[l * 8 + myh];
            acc += a * (sf[l * 3] * w0 + sf[l * 3 + 1] * w1 + sf[l * 3 + 2] * w2);
        }
        __syncthreads();
    }

    const float f0 = fea[n * 3 + 0], f1 = fea[n * 3 + 1], f2 = fea[n * 3 + 2];
    float v = acc + (f0 * s0 + f1 * s1 + f2 * s2) + b0[tid];
    v = (v > 0.f) ? v : expm1f(v);
    out[n * 512 + hidx(tid)] = __float2half_rn(v);
}

// ---------------- layer 1 scores ----------------
__global__ __launch_bounds__(256)
void scores1_kernel(const __half2* __restrict__ x1h2) {
    __shared__ float cs[4096], ct[4096];
    const int tid = threadIdx.x;
    for (int i = tid; i < 4096; i += 256) { cs[i] = g_c1[i]; ct[i] = g_c1[4096 + i]; }
    __syncthreads();
    const int warp = tid >> 5, lane = tid & 31;
    const int gw = blockIdx.x * 8 + warp;
    for (int rep = 0; rep < 8; rep++) {
        const int n = gw * 8 + rep;
        float as[8] = {0, 0, 0, 0, 0, 0, 0, 0};
        float at[8] = {0, 0, 0, 0, 0, 0, 0, 0};
        for (int i = lane; i < 256; i += 32) {
            __half2 v2 = x1h2[(size_t)n * 256 + i];
            float vlo = __low2float(v2), vhi = __high2float(v2);
#pragma unroll
            for (int h = 0; h < 8; h++) {
                as[h] += vlo * cs[h * 512 + 2 * i] + vhi * cs[h * 512 + 2 * i + 1];
                at[h] += vlo * ct[h * 512 + 2 * i] + vhi * ct[h * 512 + 2 * i + 1];
            }
        }
#pragma unroll
        for (int h = 0; h < 8; h++) {
#pragma unroll
            for (int o = 16; o; o >>= 1) {
                as[h] += __shfl_xor_sync(0xffffffffu, as[h], o);
                at[h] += __shfl_xor_sync(0xffffffffu, at[h], o);
            }
        }
        if (lane < 8) {
            g_ssrc[n * 8 + lane] = as[lane];
            g_stgt[n * 8 + lane] = at[lane];
        }
    }
}

// ---------------- layer 2 scores ----------------
__global__ __launch_bounds__(256)
void scores2_kernel(const __half2* __restrict__ x2h2) {
    __shared__ float cs[1024], ct[1024];
    const int tid = threadIdx.x;
    for (int i = tid; i < 1024; i += 256) { cs[i] = g_c2[i]; ct[i] = g_c2[1024 + i]; }
    __syncthreads();
    const int warp = tid >> 5, lane = tid & 31;
    const int n = blockIdx.x * 8 + warp;
    const __half2* row = x2h2 + (size_t)n * 512;
    float as = 0.f, at = 0.f;
    for (int i = lane; i < 512; i += 32) {
        __half2 v2 = row[i];
        float vlo = __low2float(v2), vhi = __high2float(v2);
        as += vlo * cs[2 * i] + vhi * cs[2 * i + 1];
        at += vlo * ct[2 * i] + vhi * ct[2 * i + 1];
    }
#pragma unroll
    for (int o = 16; o; o >>= 1) {
        as += __shfl_xor_sync(0xffffffffu, as, o);
        at += __shfl_xor_sync(0xffffffffu, at, o);
    }
    if (lane == 0) { g_ssrc[n] = as; g_stgt[n] = at; }
}

// ---------------- per-edge alpha, layer 1 ----------------
__global__ __launch_bounds__(256)
void alpha8_kernel() {
    const int warp = threadIdx.x >> 5, lane = threadIdx.x & 31;
    const int n = blockIdx.x * 8 + warp;
    const int beg = g_off[n], end = g_off[n + 1];
#pragma unroll
    for (int h = 0; h < 8; h++) {
        const float st = g_stgt[n * 8 + h];
        float m = -1e30f;
        for (int j = beg + lane; j < end; j += 32) {
            float e = g_ssrc[g_srcs[j] * 8 + h] + st;
            e = (e < 0.f) ? 0.2f * e : e;
            m = fmaxf(m, e);
        }
#pragma unroll
        for (int o = 16; o; o >>= 1) m = fmaxf(m, __shfl_xor_sync(0xffffffffu, m, o));
        float ss = 0.f;
        for (int j = beg + lane; j < end; j += 32) {
            float e = g_ssrc[g_srcs[j] * 8 + h] + st;
            e = (e < 0.f) ? 0.2f * e : e;
            ss += expf(e - m);
        }
#pragma unroll
        for (int o = 16; o; o >>= 1) ss += __shfl_xor_sync(0xffffffffu, ss, o);
        const float inv = 1.f / (ss + 1e-16f);
        for (int j = beg + lane; j < end; j += 32) {
            float e = g_ssrc[g_srcs[j] * 8 + h] + st;
            e = (e < 0.f) ? 0.2f * e : e;
            g_alpha[j * 8 + h] = expf(e - m) * inv;
        }
    }
}

// ---------------- per-edge alpha, layer 2 (candidates only) ----------------
__global__ __launch_bounds__(256)
void alpha1_cand_kernel(const int* __restrict__ cand) {
    const int warp = threadIdx.x >> 5, lane = threadIdx.x & 31;
    const int n = cand[blockIdx.x * 8 + warp];
    const int beg = g_off[n], end = g_off[n + 1];
    const float st = g_stgt[n];
    float m = -1e30f;
    for (int j = beg + lane; j < end; j += 32) {
        float e = g_ssrc[g_srcs[j]] + st;
        e = (e < 0.f) ? 0.2f * e : e;
        m = fmaxf(m, e);
    }
#pragma unroll
    for (int o = 16; o; o >>= 1) m = fmaxf(m, __shfl_xor_sync(0xffffffffu, m, o));
    float ss = 0.f;
    for (int j = beg + lane; j < end; j += 32) {
        float e = g_ssrc[g_srcs[j]] + st;
        e = (e < 0.f) ? 0.2f * e : e;
        ss += expf(e - m);
    }
#pragma unroll
    for (int o = 16; o; o >>= 1) ss += __shfl_xor_sync(0xffffffffu, ss, o);
    const float inv = 1.f / (ss + 1e-16f);
    for (int j = beg + lane; j < end; j += 32) {
        float e = g_ssrc[g_srcs[j]] + st;
        e = (e < 0.f) ? 0.2f * e : e;
        g_alpha[j] = expf(e - m) * inv;
    }
}

// ---------------- layer-1 aggregate ----------------
__global__ __launch_bounds__(256)
void agg1_kernel(const uint2* __restrict__ projh, const uint2* __restrict__ skiph,
                 const float4* __restrict__ bias4, __half* __restrict__ out) {
    const int n = blockIdx.x;
    const int tid = threadIdx.x;
    const int beg = g_off[n], end = g_off[n + 1];
    const int h = tid >> 5;

    float4 acc = make_float4(0.f, 0.f, 0.f, 0.f);
    for (int j = beg; j < end; j++) {
        const int s = g_srcs[j];
        const float a = g_alpha[j * 8 + h];
        const uint2 u = projh[(size_t)s * 256 + tid];
        const float2 p0 = __half22float2(*reinterpret_cast<const __half2*>(&u.x));
        const float2 p1 = __half22float2(*reinterpret_cast<const __half2*>(&u.y));
        acc.x += a * p0.x; acc.y += a * p0.y;
        acc.z += a * p1.x; acc.w += a * p1.y;
    }
    const uint2 us = skiph[(size_t)n * 256 + tid];
    const float2 s0 = __half22float2(*reinterpret_cast<const __half2*>(&us.x));
    const float2 s1 = __half22float2(*reinterpret_cast<const __half2*>(&us.y));
    const float4 bb = bias4[tid];
    float v0 = acc.x + s0.x + bb.x;
    float v1 = acc.y + s0.y + bb.y;
    float v2 = acc.z + s1.x + bb.z;
    float v3 = acc.w + s1.y + bb.w;
    v0 = (v0 > 0.f) ? v0 : expm1f(v0);
    v1 = (v1 > 0.f) ? v1 : expm1f(v1);
    v2 = (v2 > 0.f) ? v2 : expm1f(v2);
    v3 = (v3 > 0.f) ? v3 : expm1f(v3);
    const int k0 = tid * 4;
    __half* o = out + (size_t)n * 1024;
    *reinterpret_cast<__half2*>(&o[hidx(k0)])     = __floats2half2_rn(v0, v1);
    *reinterpret_cast<__half2*>(&o[hidx(k0 + 2)]) = __floats2half2_rn(v2, v3);
}

// ---------------- cp.async helpers ----------------
__device__ __forceinline__ void cp16(void* s, const void* g) {
    uint32_t sa = (uint32_t)__cvta_generic_to_shared(s);
    asm volatile("cp.async.cg.shared.global [%0], [%1], 16;\n" :: "r"(sa), "l"(g));
}
__device__ __forceinline__ void cp_commit() { asm volatile("cp.async.commit_group;\n"); }

// ---------------- dual-B FP16 GEMM (layer 1) ----------------
template <int BN, int HOUT>
__global__ __launch_bounds__(256, 1)
void gemm_dualH_kernel(const uint32_t* __restrict__ A,
                       const uint32_t* __restrict__ B0t, const uint32_t* __restrict__ B1t,
                       float* __restrict__ C0, float* __restrict__ C1,
                       int N, int Ku, int M) {
    constexpr int BM = 128, BKu = 32, ST = 40;
    constexpr int WN = BN / 2;
    constexpr int NT = WN / 8;
    constexpr int AW = BM * ST;
    constexpr int BW = BN * ST;
    constexpr int STW = AW + 2 * BW;

    extern __shared__ uint32_t sm[];

    const int tid = threadIdx.x;
    const int warp = tid >> 5, lane = tid & 31;
    const int g = lane >> 2, tig = lane & 3;
    const int half_ = warp >> 2;
    const int wsub = warp & 3;
    const int wy = wsub >> 1, wx = wsub & 1;
    const int row0 = blockIdx.y * BM;
    const int col0 = blockIdx.x * BN;
    float* Cm = half_ ? C1 : C0;

    float acc[4][NT][4];
#pragma unroll
    for (int i = 0; i < 4; i++)
#pragma unroll
        for (int j = 0; j < NT; j++)
#pragma unroll
            for (int q = 0; q < 4; q++) acc[i][j][q] = 0.f;

    const int KT = Ku / BKu;

    auto load_stage = [&](int s, int c) {
        const int k0 = c * BKu;
        uint32_t* as = sm + s * STW;
#pragma unroll
        for (int it = 0; it < 4; it++) {
            int idx = tid + it * 256;
            int r = idx >> 3, q = idx & 7;
            cp16(&as[r * ST + q * 4], &A[(size_t)(row0 + r) * Ku + k0 + q * 4]);
        }
        uint32_t* bs0 = as + AW;
        uint32_t* bs1 = bs0 + BW;
#pragma unroll
        for (int it = 0; it < BN * 8 / 256; it++) {
            int idx = tid + it * 256;
            int r = idx >> 3, q = idx & 7;
            size_t go = (size_t)(col0 + r) * Ku + k0 + q * 4;
            cp16(&bs0[r * ST + q * 4], &B0t[go]);
            cp16(&bs1[r * ST + q * 4], &B1t[go]);
        }
        cp_commit();
    };

    load_stage(0, 0);
    load_stage(1, 1);

    for (int c = 0; c < KT; c++) {
        if (c + 2 < KT) {
            load_stage((c + 2) % 3, c + 2);
            asm volatile("cp.async.wait_group 2;\n");
        } else {
            asm volatile("cp.async.wait_group 0;\n");
        }
        __syncthreads();

        const uint32_t* as = sm + (c % 3) * STW;
        const uint32_t* bs = as + AW + half_ * BW;
#pragma unroll
        for (int kk = 0; kk < BKu; kk += 8) {
            uint2 a0[4], a1[4], b[NT];
            const int ko = kk + 2 * tig;
#pragma unroll
            for (int mt = 0; mt < 4; mt++) {
                int br = wy * 64 + mt * 16;
                a0[mt] = *reinterpret_cast<const uint2*>(&as[(br + g) * ST + ko]);
                a1[mt] = *reinterpret_cast<const uint2*>(&as[(br + g + 8) * ST + ko]);
            }
#pragma unroll
            for (int nt = 0; nt < NT; nt++) {
                int bc = wx * WN + nt * 8;
                b[nt] = *reinterpret_cast<const uint2*>(&bs[(bc + g) * ST + ko]);
            }
#pragma unroll
            for (int mt = 0; mt < 4; mt++)
#pragma unroll
                for (int nt = 0; nt < NT; nt++) {
                    asm volatile(
                        "mma.sync.aligned.m16n8k16.row.col.f32.f16.f16.f32 "
                        "{%0,%1,%2,%3}, {%4,%5,%6,%7}, {%8,%9}, {%0,%1,%2,%3};\n"
                        : "+f"(acc[mt][nt][0]), "+f"(acc[mt][nt][1]),
                          "+f"(acc[mt][nt][2]), "+f"(acc[mt][nt][3])
                        : "r"(a0[mt].x), "r"(a1[mt].x), "r"(a0[mt].y), "r"(a1[mt].y),
                          "r"(b[nt].x), "r"(b[nt].y));
                }
        }
        __syncthreads();
    }

#pragma unroll
    for (int mt = 0; mt < 4; mt++) {
#pragma unroll
        for (int nt = 0; nt < NT; nt++) {
            int r = row0 + wy * 64 + mt * 16 + g;
            int cc = col0 + wx * WN + nt * 8 + tig * 2;
            if (HOUT) {
                __half2* Cm2 = reinterpret_cast<__half2*>(Cm);
                Cm2[(size_t)r * (M / 2) + cc / 2] =
                    __floats2half2_rn(acc[mt][nt][0], acc[mt][nt][1]);
                Cm2[(size_t)(r + 8) * (M / 2) + cc / 2] =
                    __floats2half2_rn(acc[mt][nt][2], acc[mt][nt][3]);
            } else {
                *reinterpret_cast<float2*>(&Cm[(size_t)r * M + cc]) =
                    make_float2(acc[mt][nt][0], acc[mt][nt][1]);
                *reinterpret_cast<float2*>(&Cm[(size_t)(r + 8) * M + cc]) =
                    make_float2(acc[mt][nt][2], acc[mt][nt][3]);
            }
        }
    }
}

// ---------------- single-B FP16 GEMM (layer 2 proj): BM=256, BN=64 ----------------
__global__ __launch_bounds__(256, 1)
void gemm_singleH_kernel(const uint32_t* __restrict__ A, const uint32_t* __restrict__ Bt,
                         float* __restrict__ C, int Ku, int M) {
    constexpr int BM = 256, BN = 64, BKu = 32, ST = 40;
    constexpr int NT = 4;                     // 32 cols per warp
    constexpr int AW = BM * ST;
    constexpr int BW = BN * ST;
    constexpr int STW = AW + BW;

    extern __shared__ uint32_t sm[];

    const int tid = threadIdx.x;
    const int warp = tid >> 5, lane = tid & 31;
    const int g = lane >> 2, tig = lane & 3;
    const int wy = warp >> 1, wx = warp & 1;  // 4 x 2 warps: 64 rows x 32 cols each
    const int row0 = blockIdx.y * BM;

    float acc[4][NT][4];
#pragma unroll
    for (int i = 0; i < 4; i++)
#pragma unroll
        for (int j = 0; j < NT; j++)
#pragma unroll
            for (int q = 0; q < 4; q++) acc[i][j][q] = 0.f;

    const int KT = Ku / BKu;

    auto load_stage = [&](int s, int c) {
        const int k0 = c * BKu;
        uint32_t* as = sm + s * STW;
#pragma unroll
        for (int it = 0; it < 8; it++) {      // 2048 A quads
            int idx = tid + it * 256;
            int r = idx >> 3, q = idx & 7;
            cp16(&as[r * ST + q * 4], &A[(size_t)(row0 + r) * Ku + k0 + q * 4]);
        }
        uint32_t* bs = as + AW;
#pragma unroll
        for (int it = 0; it < 2; it++) {      // 512 B quads
            int idx = tid + it * 256;
            int r = idx >> 3, q = idx & 7;
            cp16(&bs[r * ST + q * 4], &Bt[(size_t)r * Ku + k0 + q * 4]);
        }
        cp_commit();
    };

    load_stage(0, 0);
    load_stage(1, 1);

    for (int c = 0; c < KT; c++) {
        if (c + 2 < KT) {
            load_stage((c + 2) % 3, c + 2);
            asm volatile("cp.async.wait_group 2;\n");
        } else {
            asm volatile("cp.async.wait_group 0;\n");
        }
        __syncthreads();

        const uint32_t* as = sm + (c % 3) * STW;
        const uint32_t* bs = as + AW;
#pragma unroll
        for (int kk = 0; kk < BKu; kk += 8) {
            uint2 a0[4], a1[4], b[NT];
            const int ko = kk + 2 * tig;
#pragma unroll
            for (int mt = 0; mt < 4; mt++) {
                int br = wy * 64 + mt * 16;
                a0[mt] = *reinterpret_cast<const uint2*>(&as[(br + g) * ST + ko]);
                a1[mt] = *reinterpret_cast<const uint2*>(&as[(br + g + 8) * ST + ko]);
            }
#pragma unroll
            for (int nt = 0; nt < NT; nt++) {
                int bc = wx * 32 + nt * 8;
                b[nt] = *reinterpret_cast<const uint2*>(&bs[(bc + g) * ST + ko]);
            }
#pragma unroll
            for (int mt = 0; mt < 4; mt++)
#pragma unroll
                for (int nt = 0; nt < NT; nt++) {
                    asm volatile(
                        "mma.sync.aligned.m16n8k16.row.col.f32.f16.f16.f32 "
                        "{%0,%1,%2,%3}, {%4,%5,%6,%7}, {%8,%9}, {%0,%1,%2,%3};\n"
                        : "+f"(acc[mt][nt][0]), "+f"(acc[mt][nt][1]),
                          "+f"(acc[mt][nt][2]), "+f"(acc[mt][nt][3])
                        : "r"(a0[mt].x), "r"(a1[mt].x), "r"(a0[mt].y), "r"(a1[mt].y),
                          "r"(b[nt].x), "r"(b[nt].y));
                }
        }
        __syncthreads();
    }

#pragma unroll
    for (int mt = 0; mt < 4; mt++) {
#pragma unroll
        for (int nt = 0; nt < NT; nt++) {
            int r = row0 + wy * 64 + mt * 16 + g;
            int cc = wx * 32 + nt * 8 + tig * 2;
            *reinterpret_cast<float2*>(&C[(size_t)r * M + cc]) =
                make_float2(acc[mt][nt][0], acc[mt][nt][1]);
            *reinterpret_cast<float2*>(&C[(size_t)(r + 8) * M + cc]) =
                make_float2(acc[mt][nt][2], acc[mt][nt][3]);
        }
    }
}

// ---------------- candidate skip GEMV: zskip[c] = x2[cand[c]] @ S2 ----------------
__global__ __launch_bounds__(256)
void skip2c_kernel(const __half2* __restrict__ x2h2, const float* __restrict__ S2,
                   const int* __restrict__ cand, float* __restrict__ zskip) {
    __shared__ float xs[1024];
    __shared__ float red[4][64];
    const int c = blockIdx.x;
    const int n = cand[c];
    const int tid = threadIdx.x;
    for (int i = tid; i < 512; i += 256) {
        __half2 v = x2h2[(size_t)n * 512 + i];
        xs[2 * i] = __low2float(v);
        xs[2 * i + 1] = __high2float(v);
    }
    __syncthreads();
    const int j = tid & 63, part = tid >> 6;
    float acc = 0.f;
    const int kb = part * 256;
#pragma unroll 4
    for (int k = kb; k < kb + 256; k++)
        acc += xs[hidx(k)] * S2[(size_t)k * 64 + j];
    red[part][j] = acc;
    __syncthreads();
    if (part == 0)
        zskip[(size_t)c * 64 + j] = red[0][j] + red[1][j] + red[2][j] + red[3][j];
}

// ---------------- layer-2 candidate-only aggregate ----------------
__global__ __launch_bounds__(256)
void agg2_cand_kernel(const float* __restrict__ proj, const float* __restrict__ zskip,
                      const float* __restrict__ bias, const int* __restrict__ cand,
                      float* __restrict__ z) {
    const int c = blockIdx.x * 4 + (threadIdx.x >> 6);
    const int col = threadIdx.x & 63;
    const int n = cand[c];
    const int beg = g_off[n], end = g_off[n + 1];
    float acc = 0.f;
    for (int j = beg; j < end; j++)
        acc += g_alpha[j] * proj[(size_t)g_srcs[j] * 64 + col];
    z[(size_t)c * 64 + col] = acc + zskip[(size_t)c * 64 + col] + bias[col];
}

// ---------------- MLP head ----------------
__global__ void mlp_kernel(const float* __restrict__ z, const int* __restrict__ cand,
                           const float* __restrict__ mW1, const float* __restrict__ mb1,
                           const float* __restrict__ mW2, const float* __restrict__ mb2,
                           const float* __restrict__ mW3, const float* __restrict__ mb3,
                           float* __restrict__ out, int out_size) {
    int c = blockIdx.x;
    int tid = threadIdx.x;
    __shared__ float sc[64];
    __shared__ float sh[256];
    if (tid < 64) sc[tid] = z[c * 64 + tid];
    __syncthreads();

    float acc = mb1[tid];
#pragma unroll 8
    for (int k = 0; k < 64; k++) acc += sc[k] * mW1[k * 256 + tid];
    float h1 = tanhf(acc);
    sh[tid] = h1;
    __syncthreads();

    acc = mb2[tid];
#pragma unroll 8
    for (int k = 0; k < 256; k++) acc += sh[k] * mW2[k * 256 + tid];
    float h2 = tanhf(acc);
    __syncthreads();

    sh[tid] = h2 * mW3[tid];
    __syncthreads();
    for (int s = 128; s; s >>= 1) {
        if (tid < s) sh[tid] += sh[tid + s];
        __syncthreads();
    }
    if (tid == 0) out[c] = sh[0] + mb3[0];
    if (out_size > NCAND && tid == 1 && (NCAND + c) < out_size) {
        out[NCAND + c] = (float)cand[c];
    }
}

// ---------------- launch ----------------
extern "C" void kernel_launch(void* const* d_in, const int* in_sizes, int n_in,
                              void* d_out, int out_size) {
    const float* fea  = (const float*)d_in[0];
    const int*   ei   = (const int*)d_in[1];
    const int*   cand = (const int*)d_in[2];
    const float* W0 = (const float*)d_in[3];
    const float* a_src0 = (const float*)d_in[4];
    const float* a_tgt0 = (const float*)d_in[5];
    const float* b0 = (const float*)d_in[6];
    const float* skip0 = (const float*)d_in[7];
    const float* W1 = (const float*)d_in[8];
    const float* a_src1 = (const float*)d_in[9];
    const float* a_tgt1 = (const float*)d_in[10];
    const float* b1 = (const float*)d_in[11];
    const float* skip1 = (const float*)d_in[12];
    const float* W2 = (const float*)d_in[13];
    const float* a_src2 = (const float*)d_in[14];
    const float* a_tgt2 = (const float*)d_in[15];
    const float* b2 = (const float*)d_in[16];
    const float* skip2 = (const float*)d_in[17];
    const float* mW1 = (const float*)d_in[18];
    const float* mb1 = (const float*)d_in[19];
    const float* mW2 = (const float*)d_in[20];
    const float* mb2 = (const float*)d_in[21];
    const float* mW3 = (const float*)d_in[22];
    const float* mb3 = (const float*)d_in[23];

    const int E = in_sizes[1] / 2;
    const int* src = ei;
    const int* tgt = ei + E;

    float *x1, *x2, *x3, *proj, *skip;
    uint32_t* wtf;
    cudaGetSymbolAddress((void**)&x1,   g_x1);
    cudaGetSymbolAddress((void**)&x2,   g_x2);
    cudaGetSymbolAddress((void**)&x3,   g_x3);
    cudaGetSymbolAddress((void**)&proj, g_proj);
    cudaGetSymbolAddress((void**)&skip, g_skip);
    cudaGetSymbolAddress((void**)&wtf,  g_wtf);

    uint32_t* W1t = wtf;
    uint32_t* S1t = wtf + 262144;
    uint32_t* W2t = wtf + 524288;

    const int SMEM_L1 = 3 * (128 * 40 + 2 * 128 * 40) * 4;  // 184320
    const int SMEM_L2 = 3 * (256 * 40 + 64 * 40) * 4;       // 153600
    cudaFuncSetAttribute(gemm_dualH_kernel<128, 1>,
                         cudaFuncAttributeMaxDynamicSharedMemorySize, SMEM_L1);
    cudaFuncSetAttribute(gemm_singleH_kernel,
                         cudaFuncAttributeMaxDynamicSharedMemorySize, SMEM_L2);

    // ---- merged setup ----
    setup1_kernel<<<1193, 256>>>(W1, skip1, W2, W0,
                                 a_src0, a_tgt0, a_src1, a_tgt1, a_src2, a_tgt2,
                                 (__half*)W1t, (__half*)S1t, (__half*)W2t);
    setup2_kernel<<<896, 256>>>(tgt, fea);
    scan_kernel<<<1, 1024>>>();
    scatter_kernel<<<(NEDGES + 255) / 256, 256>>>(src, tgt);

    // ---- layer 0 fused agg ----
    agg0_kernel<<<NNODES, 512>>>(fea, W0, skip0, b0, (__half*)x1);

    // ---- layer 1 ----
    scores1_kernel<<<256, 256>>>((const __half2*)x1);
    alpha8_kernel<<<NNODES / 8, 256>>>();
    gemm_dualH_kernel<128, 1><<<dim3(8, NNODES / 128), 256, SMEM_L1>>>(
        (const uint32_t*)x1, W1t, S1t, proj, skip, NNODES, 256, 1024);
    agg1_kernel<<<NNODES, 256>>>((const uint2*)proj, (const uint2*)skip,
                                 (const float4*)b1, (__half*)x2);

    // ---- layer 2: single-B proj GEMM + candidate skip GEMV + candidate tail ----
    scores2_kernel<<<NNODES / 8, 256>>>((const __half2*)x2);
    alpha1_cand_kernel<<<NCAND / 8, 256>>>(cand);
    skip2c_kernel<<<NCAND, 256>>>((const __half2*)x2, skip2, cand, skip /*zskip*/);
    gemm_singleH_kernel<<<dim3(1, NNODES / 256), 256, SMEM_L2>>>(
        (const uint32_t*)x2, W2t, proj, 512, 64);
    agg2_cand_kernel<<<NCAND / 4, 256>>>(proj, skip, b2, cand, x3);

    // ---- MLP head ----
    mlp_kernel<<<NCAND, 256>>>(x3, cand, mW1, mb1, mW2, mb2, mW3, mb3, (float*)d_out, out_size);
}

// round 17
// speedup vs baseline: 1.0939x; 1.0939x over previous
#include <cuda_runtime.h>
#include <cuda_fp16.h>
#include <math.h>
#include <stdint.h>

#define NNODES 16384
#define NEDGES 98304
#define NCAND  1024

__device__ __forceinline__ int hidx(int k) {
    int kp = k >> 1, s = kp & 7;
    return ((kp >> 3) << 4) + ((((s & 3) << 1) | (s >> 2)) << 1) + (k & 1);
}

// ---------------- scratch ----------------
__device__ float g_x1[NNODES * 512];
__device__ float g_x2[NNODES * 1024];
__device__ float g_x3[NCAND * 64];
__device__ float g_proj[NNODES * 1024];
__device__ float g_skip[NNODES * 1024];
__device__ float g_ssrc[NNODES * 8];
__device__ float g_stgt[NNODES * 8];
__device__ float g_alpha[NEDGES * 8];
__device__ int   g_cnt[NNODES];
__device__ int   g_off[NNODES + 1];
__device__ int   g_cur[NNODES];
__device__ int   g_srcs[NEDGES];
__device__ float g_csrc[24];
__device__ float g_ctgt[24];
__device__ float g_c1[8192];
__device__ float g_c2[2048];             // layer2 fold, hidx layout: src[1024], tgt[1024]
__device__ uint32_t g_wtf[1179648];

// ---------------- merged setup kernel 1 ----------------
__device__ void convTP_dev(const float* __restrict__ in, __half* __restrict__ out,
                           int K, int M, int bx, int by, int tid) {
    __shared__ float t[32][33];
    const int k0 = bx * 32, m0 = by * 32;
    const int tx = tid & 31, ty = tid >> 5;
    for (int i = ty; i < 32; i += 8)
        t[i][tx] = in[(size_t)(k0 + i) * M + m0 + tx];
    __syncthreads();
    for (int i = ty; i < 32; i += 8) {
        int m = m0 + i, k = k0 + tx;
        out[(size_t)m * K + hidx(k)] = __float2half_rn(t[tx][i]);
    }
}

__global__ __launch_bounds__(256)
void setup1_kernel(const float* __restrict__ W1, const float* __restrict__ S1,
                   const float* __restrict__ W2, const float* __restrict__ S2,
                   const float* __restrict__ W0,
                   const float* __restrict__ a_src0, const float* __restrict__ a_tgt0,
                   const float* __restrict__ a_src1, const float* __restrict__ a_tgt1,
                   const float* __restrict__ a_src2, const float* __restrict__ a_tgt2,
                   __half* __restrict__ W1t, __half* __restrict__ S1t,
                   __half* __restrict__ W2t, __half* __restrict__ S2t) {
    const int b = blockIdx.x;
    const int tid = threadIdx.x;
    if (b < 512) {
        convTP_dev(W1, W1t, 512, 1024, b & 15, b >> 4, tid);
    } else if (b < 1024) {
        int bb = b - 512;
        convTP_dev(S1, S1t, 512, 1024, bb & 15, bb >> 4, tid);
    } else if (b < 1088) {
        int bb = b - 1024;
        convTP_dev(W2, W2t, 1024, 64, bb & 31, bb >> 5, tid);
    } else if (b < 1152) {
        int bb = b - 1088;
        convTP_dev(S2, S2t, 1024, 64, bb & 31, bb >> 5, tid);
    } else if (b < 1216) {
        int i = (b - 1152) * 256 + tid;
        if (i < NNODES) g_cnt[i] = 0;
    } else if (b < 1248) {
        int t = (b - 1216) * 256 + tid;
        int isT = t >= 4096;
        int i = t & 4095;
        int h = i >> 9, k = i & 511;
        const float* a = isT ? a_tgt1 : a_src1;
        float s = 0.f;
#pragma unroll 4
        for (int f = 0; f < 128; f++)
            s += W1[(size_t)k * 1024 + h * 128 + f] * a[h * 128 + f];
        g_c1[isT * 4096 + h * 512 + hidx(k)] = s;
    } else if (b < 1256) {
        int t = (b - 1248) * 256 + tid;
        int isT = t >= 1024;
        int k = t & 1023;
        const float* a = isT ? a_tgt2 : a_src2;
        float s = 0.f;
#pragma unroll 8
        for (int f = 0; f < 64; f++) s += W2[(size_t)k * 64 + f] * a[f];
        g_c2[isT * 1024 + hidx(k)] = s;
    } else {
        if (tid < 48) {
            int isT = tid >= 24;
            int i = isT ? tid - 24 : tid;
            int h = i / 3, d = i % 3;
            const float* a = isT ? a_tgt0 : a_src0;
            float s = 0.f;
            for (int f = 0; f < 64; f++)
                s += W0[d * 512 + h * 64 + f] * a[h * 64 + f];
            (isT ? g_ctgt : g_csrc)[i] = s;
        }
    }
}

// ---------------- merged setup kernel 2: count + l0_scores ----------------
__global__ __launch_bounds__(256)
void setup2_kernel(const int* __restrict__ tgt, const float* __restrict__ fea) {
    const int b = blockIdx.x;
    const int tid = threadIdx.x;
    if (b < 384) {
        int e = b * 256 + tid;
        if (e < NEDGES) atomicAdd(&g_cnt[tgt[e]], 1);
    } else {
        int i = (b - 384) * 256 + tid;
        if (i < NNODES * 8) {
            int n = i >> 3, h = i & 7;
            float f0 = fea[n * 3 + 0], f1 = fea[n * 3 + 1], f2 = fea[n * 3 + 2];
            g_ssrc[i] = f0 * g_csrc[h * 3] + f1 * g_csrc[h * 3 + 1] + f2 * g_csrc[h * 3 + 2];
            g_stgt[i] = f0 * g_ctgt[h * 3] + f1 * g_ctgt[h * 3 + 1] + f2 * g_ctgt[h * 3 + 2];
        }
    }
}

__global__ void scan_kernel() {
    __shared__ int part[1024];
    const int PER = NNODES / 1024;
    int tid = threadIdx.x;
    int base = tid * PER;
    int local[PER];
    int s = 0;
#pragma unroll
    for (int i = 0; i < PER; i++) { local[i] = g_cnt[base + i]; s += local[i]; }
    part[tid] = s;
    __syncthreads();
    for (int d = 1; d < 1024; d <<= 1) {
        int v = (tid >= d) ? part[tid - d] : 0;
        __syncthreads();
        part[tid] += v;
        __syncthreads();
    }
    int run = (tid == 0) ? 0 : part[tid - 1];
#pragma unroll
    for (int i = 0; i < PER; i++) {
        g_off[base + i] = run;
        g_cur[base + i] = run;
        run += local[i];
    }
    if (tid == 1023) g_off[NNODES] = run;
}
__global__ void scatter_kernel(const int* __restrict__ src, const int* __restrict__ tgt) {
    int e = blockIdx.x * blockDim.x + threadIdx.x;
    if (e < NEDGES) {
        int p = atomicAdd(&g_cur[tgt[e]], 1);
        g_srcs[p] = src[e];
    }
}

// ---------------- fused layer 0 agg ----------------
__global__ __launch_bounds__(512)
void agg0_kernel(const float* __restrict__ fea,
                 const float* __restrict__ W0, const float* __restrict__ S0,
                 const float* __restrict__ b0, __half* __restrict__ out) {
    const int n = blockIdx.x;
    const int tid = threadIdx.x;
    const int warp = tid >> 5, lane = tid & 31;
    const int beg = g_off[n], end = g_off[n + 1];

    const float w0 = W0[tid], w1 = W0[512 + tid], w2 = W0[1024 + tid];
    const float s0 = S0[tid], s1 = S0[512 + tid], s2 = S0[1024 + tid];

    __shared__ float mh[8], ivh[8];
    __shared__ float al[32 * 8];
    __shared__ float sf[32 * 3];

    if (warp < 8) {
        const int h = warp;
        const float st = g_stgt[n * 8 + h];
        float m = -1e30f;
        for (int j = beg + lane; j < end; j += 32) {
            float e = g_ssrc[g_srcs[j] * 8 + h] + st;
            e = (e < 0.f) ? 0.2f * e : e;
            m = fmaxf(m, e);
        }
#pragma unroll
        for (int o = 16; o; o >>= 1) m = fmaxf(m, __shfl_xor_sync(0xffffffffu, m, o));
        float ss = 0.f;
        for (int j = beg + lane; j < end; j += 32) {
            float e = g_ssrc[g_srcs[j] * 8 + h] + st;
            e = (e < 0.f) ? 0.2f * e : e;
            ss += expf(e - m);
        }
#pragma unroll
        for (int o = 16; o; o >>= 1) ss += __shfl_xor_sync(0xffffffffu, ss, o);
        if (lane == 0) { mh[h] = m; ivh[h] = 1.f / (ss + 1e-16f); }
    }
    __syncthreads();

    const int myh = tid >> 6;
    float acc = 0.f;
    for (int j0 = beg; j0 < end; j0 += 32) {
        const int nj = min(32, end - j0);
        if (tid < 256) {
            const int l = tid & 31, h = tid >> 5;
            if (l < nj) {
                const int s = g_srcs[j0 + l];
                const float st = g_stgt[n * 8 + h];
                float e = g_ssrc[s * 8 + h] + st;
                e = (e < 0.f) ? 0.2f * e : e;
                al[l * 8 + h] = expf(e - mh[h]) * ivh[h];
                if (h == 0) {
                    sf[l * 3 + 0] = fea[s * 3 + 0];
                    sf[l * 3 + 1] = fea[s * 3 + 1];
                    sf[l * 3 + 2] = fea[s * 3 + 2];
                }
            }
        }
        __syncthreads();
        for (int l = 0; l < nj; l++) {
            const float a = al[l * 8 + myh];
            acc += a * (sf[l * 3] * w0 + sf[l * 3 + 1] * w1 + sf[l * 3 + 2] * w2);
        }
        __syncthreads();
    }

    const float f0 = fea[n * 3 + 0], f1 = fea[n * 3 + 1], f2 = fea[n * 3 + 2];
    float v = acc + (f0 * s0 + f1 * s1 + f2 * s2) + b0[tid];
    v = (v > 0.f) ? v : expm1f(v);
    out[n * 512 + hidx(tid)] = __float2half_rn(v);
}

// ---------------- layer 1 scores ----------------
__global__ __launch_bounds__(256)
void scores1_kernel(const __half2* __restrict__ x1h2) {
    __shared__ float cs[4096], ct[4096];
    const int tid = threadIdx.x;
    for (int i = tid; i < 4096; i += 256) { cs[i] = g_c1[i]; ct[i] = g_c1[4096 + i]; }
    __syncthreads();
    const int warp = tid >> 5, lane = tid & 31;
    const int gw = blockIdx.x * 8 + warp;
    for (int rep = 0; rep < 8; rep++) {
        const int n = gw * 8 + rep;
        float as[8] = {0, 0, 0, 0, 0, 0, 0, 0};
        float at[8] = {0, 0, 0, 0, 0, 0, 0, 0};
        for (int i = lane; i < 256; i += 32) {
            __half2 v2 = x1h2[(size_t)n * 256 + i];
            float vlo = __low2float(v2), vhi = __high2float(v2);
#pragma unroll
            for (int h = 0; h < 8; h++) {
                as[h] += vlo * cs[h * 512 + 2 * i] + vhi * cs[h * 512 + 2 * i + 1];
                at[h] += vlo * ct[h * 512 + 2 * i] + vhi * ct[h * 512 + 2 * i + 1];
            }
        }
#pragma unroll
        for (int h = 0; h < 8; h++) {
#pragma unroll
            for (int o = 16; o; o >>= 1) {
                as[h] += __shfl_xor_sync(0xffffffffu, as[h], o);
                at[h] += __shfl_xor_sync(0xffffffffu, at[h], o);
            }
        }
        if (lane < 8) {
            g_ssrc[n * 8 + lane] = as[lane];
            g_stgt[n * 8 + lane] = at[lane];
        }
    }
}

// ---------------- per-edge alpha, layer 1 ----------------
__global__ __launch_bounds__(256)
void alpha8_kernel() {
    const int warp = threadIdx.x >> 5, lane = threadIdx.x & 31;
    const int n = blockIdx.x * 8 + warp;
    const int beg = g_off[n], end = g_off[n + 1];
#pragma unroll
    for (int h = 0; h < 8; h++) {
        const float st = g_stgt[n * 8 + h];
        float m = -1e30f;
        for (int j = beg + lane; j < end; j += 32) {
            float e = g_ssrc[g_srcs[j] * 8 + h] + st;
            e = (e < 0.f) ? 0.2f * e : e;
            m = fmaxf(m, e);
        }
#pragma unroll
        for (int o = 16; o; o >>= 1) m = fmaxf(m, __shfl_xor_sync(0xffffffffu, m, o));
        float ss = 0.f;
        for (int j = beg + lane; j < end; j += 32) {
            float e = g_ssrc[g_srcs[j] * 8 + h] + st;
            e = (e < 0.f) ? 0.2f * e : e;
            ss += expf(e - m);
        }
#pragma unroll
        for (int o = 16; o; o >>= 1) ss += __shfl_xor_sync(0xffffffffu, ss, o);
        const float inv = 1.f / (ss + 1e-16f);
        for (int j = beg + lane; j < end; j += 32) {
            float e = g_ssrc[g_srcs[j] * 8 + h] + st;
            e = (e < 0.f) ? 0.2f * e : e;
            g_alpha[j * 8 + h] = expf(e - m) * inv;
        }
    }
}

// ---------------- per-edge alpha, layer 2 (candidates only) ----------------
__global__ __launch_bounds__(256)
void alpha1_cand_kernel(const int* __restrict__ cand) {
    const int warp = threadIdx.x >> 5, lane = threadIdx.x & 31;
    const int n = cand[blockIdx.x * 8 + warp];
    const int beg = g_off[n], end = g_off[n + 1];
    const float st = g_stgt[n];
    float m = -1e30f;
    for (int j = beg + lane; j < end; j += 32) {
        float e = g_ssrc[g_srcs[j]] + st;
        e = (e < 0.f) ? 0.2f * e : e;
        m = fmaxf(m, e);
    }
#pragma unroll
    for (int o = 16; o; o >>= 1) m = fmaxf(m, __shfl_xor_sync(0xffffffffu, m, o));
    float ss = 0.f;
    for (int j = beg + lane; j < end; j += 32) {
        float e = g_ssrc[g_srcs[j]] + st;
        e = (e < 0.f) ? 0.2f * e : e;
        ss += expf(e - m);
    }
#pragma unroll
    for (int o = 16; o; o >>= 1) ss += __shfl_xor_sync(0xffffffffu, ss, o);
    const float inv = 1.f / (ss + 1e-16f);
    for (int j = beg + lane; j < end; j += 32) {
        float e = g_ssrc[g_srcs[j]] + st;
        e = (e < 0.f) ? 0.2f * e : e;
        g_alpha[j] = expf(e - m) * inv;
    }
}

// ---------------- layer-1 aggregate + FUSED layer-2 scores ----------------
__global__ __launch_bounds__(256)
void agg1_kernel(const uint2* __restrict__ projh, const uint2* __restrict__ skiph,
                 const float4* __restrict__ bias4, __half* __restrict__ out) {
    const int n = blockIdx.x;
    const int tid = threadIdx.x;
    const int beg = g_off[n], end = g_off[n + 1];
    const int h = tid >> 5;
    const int lane = tid & 31;

    float4 acc = make_float4(0.f, 0.f, 0.f, 0.f);
    for (int j = beg; j < end; j++) {
        const int s = g_srcs[j];
        const float a = g_alpha[j * 8 + h];
        const uint2 u = projh[(size_t)s * 256 + tid];
        const float2 p0 = __half22float2(*reinterpret_cast<const __half2*>(&u.x));
        const float2 p1 = __half22float2(*reinterpret_cast<const __half2*>(&u.y));
        acc.x += a * p0.x; acc.y += a * p0.y;
        acc.z += a * p1.x; acc.w += a * p1.y;
    }
    const uint2 us = skiph[(size_t)n * 256 + tid];
    const float2 s0 = __half22float2(*reinterpret_cast<const __half2*>(&us.x));
    const float2 s1 = __half22float2(*reinterpret_cast<const __half2*>(&us.y));
    const float4 bb = bias4[tid];
    float v0 = acc.x + s0.x + bb.x;
    float v1 = acc.y + s0.y + bb.y;
    float v2 = acc.z + s1.x + bb.z;
    float v3 = acc.w + s1.y + bb.w;
    v0 = (v0 > 0.f) ? v0 : expm1f(v0);
    v1 = (v1 > 0.f) ? v1 : expm1f(v1);
    v2 = (v2 > 0.f) ? v2 : expm1f(v2);
    v3 = (v3 > 0.f) ? v3 : expm1f(v3);
    const int k0 = tid * 4;
    const int p0i = hidx(k0), p1i = hidx(k0 + 2);
    __half* o = out + (size_t)n * 1024;
    *reinterpret_cast<__half2*>(&o[p0i]) = __floats2half2_rn(v0, v1);
    *reinterpret_cast<__half2*>(&o[p1i]) = __floats2half2_rn(v2, v3);

    // fused layer-2 scores: dot(x2[n], c2_src/tgt) — c2 stored in same hidx layout
    const float2 ca0 = *reinterpret_cast<const float2*>(&g_c2[p0i]);
    const float2 ca1 = *reinterpret_cast<const float2*>(&g_c2[p1i]);
    const float2 cb0 = *reinterpret_cast<const float2*>(&g_c2[1024 + p0i]);
    const float2 cb1 = *reinterpret_cast<const float2*>(&g_c2[1024 + p1i]);
    float ps = v0 * ca0.x + v1 * ca0.y + v2 * ca1.x + v3 * ca1.y;
    float pt = v0 * cb0.x + v1 * cb0.y + v2 * cb1.x + v3 * cb1.y;
#pragma unroll
    for (int of = 16; of; of >>= 1) {
        ps += __shfl_xor_sync(0xffffffffu, ps, of);
        pt += __shfl_xor_sync(0xffffffffu, pt, of);
    }
    __shared__ float rs[8], rt[8];
    if (lane == 0) { rs[h] = ps; rt[h] = pt; }
    __syncthreads();
    if (tid == 0) {
        float S = 0.f, T = 0.f;
#pragma unroll
        for (int i = 0; i < 8; i++) { S += rs[i]; T += rt[i]; }
        g_ssrc[n] = S;
        g_stgt[n] = T;
    }
}

// ---------------- cp.async helpers ----------------
__device__ __forceinline__ void cp16(void* s, const void* g) {
    uint32_t sa = (uint32_t)__cvta_generic_to_shared(s);
    asm volatile("cp.async.cg.shared.global [%0], [%1], 16;\n" :: "r"(sa), "l"(g));
}
__device__ __forceinline__ void cp_commit() { asm volatile("cp.async.commit_group;\n"); }

// ---------------- dual-B FP16 GEMM ----------------
template <int BN, int HOUT>
__global__ __launch_bounds__(256, 1)
void gemm_dualH_kernel(const uint32_t* __restrict__ A,
                       const uint32_t* __restrict__ B0t, const uint32_t* __restrict__ B1t,
                       float* __restrict__ C0, float* __restrict__ C1,
                       int N, int Ku, int M) {
    constexpr int BM = 128, BKu = 32, ST = 40;
    constexpr int WN = BN / 2;
    constexpr int NT = WN / 8;
    constexpr int AW = BM * ST;
    constexpr int BW = BN * ST;
    constexpr int STW = AW + 2 * BW;

    extern __shared__ uint32_t sm[];

    const int tid = threadIdx.x;
    const int warp = tid >> 5, lane = tid & 31;
    const int g = lane >> 2, tig = lane & 3;
    const int half_ = warp >> 2;
    const int wsub = warp & 3;
    const int wy = wsub >> 1, wx = wsub & 1;
    const int row0 = blockIdx.y * BM;
    const int col0 = blockIdx.x * BN;
    float* Cm = half_ ? C1 : C0;

    float acc[4][NT][4];
#pragma unroll
    for (int i = 0; i < 4; i++)
#pragma unroll
        for (int j = 0; j < NT; j++)
#pragma unroll
            for (int q = 0; q < 4; q++) acc[i][j][q] = 0.f;

    const int KT = Ku / BKu;

    auto load_stage = [&](int s, int c) {
        const int k0 = c * BKu;
        uint32_t* as = sm + s * STW;
#pragma unroll
        for (int it = 0; it < 4; it++) {
            int idx = tid + it * 256;
            int r = idx >> 3, q = idx & 7;
            cp16(&as[r * ST + q * 4], &A[(size_t)(row0 + r) * Ku + k0 + q * 4]);
        }
        uint32_t* bs0 = as + AW;
        uint32_t* bs1 = bs0 + BW;
#pragma unroll
        for (int it = 0; it < BN * 8 / 256; it++) {
            int idx = tid + it * 256;
            int r = idx >> 3, q = idx & 7;
            size_t go = (size_t)(col0 + r) * Ku + k0 + q * 4;
            cp16(&bs0[r * ST + q * 4], &B0t[go]);
            cp16(&bs1[r * ST + q * 4], &B1t[go]);
        }
        cp_commit();
    };

    load_stage(0, 0);
    load_stage(1, 1);

    for (int c = 0; c < KT; c++) {
        if (c + 2 < KT) {
            load_stage((c + 2) % 3, c + 2);
            asm volatile("cp.async.wait_group 2;\n");
        } else {
            asm volatile("cp.async.wait_group 0;\n");
        }
        __syncthreads();

        const uint32_t* as = sm + (c % 3) * STW;
        const uint32_t* bs = as + AW + half_ * BW;
#pragma unroll
        for (int kk = 0; kk < BKu; kk += 8) {
            uint2 a0[4], a1[4], b[NT];
            const int ko = kk + 2 * tig;
#pragma unroll
            for (int mt = 0; mt < 4; mt++) {
                int br = wy * 64 + mt * 16;
                a0[mt] = *reinterpret_cast<const uint2*>(&as[(br + g) * ST + ko]);
                a1[mt] = *reinterpret_cast<const uint2*>(&as[(br + g + 8) * ST + ko]);
            }
#pragma unroll
            for (int nt = 0; nt < NT; nt++) {
                int bc = wx * WN + nt * 8;
                b[nt] = *reinterpret_cast<const uint2*>(&bs[(bc + g) * ST + ko]);
            }
#pragma unroll
            for (int mt = 0; mt < 4; mt++)
#pragma unroll
                for (int nt = 0; nt < NT; nt++) {
                    asm volatile(
                        "mma.sync.aligned.m16n8k16.row.col.f32.f16.f16.f32 "
                        "{%0,%1,%2,%3}, {%4,%5,%6,%7}, {%8,%9}, {%0,%1,%2,%3};\n"
                        : "+f"(acc[mt][nt][0]), "+f"(acc[mt][nt][1]),
                          "+f"(acc[mt][nt][2]), "+f"(acc[mt][nt][3])
                        : "r"(a0[mt].x), "r"(a1[mt].x), "r"(a0[mt].y), "r"(a1[mt].y),
                          "r"(b[nt].x), "r"(b[nt].y));
                }
        }
        __syncthreads();
    }

#pragma unroll
    for (int mt = 0; mt < 4; mt++) {
#pragma unroll
        for (int nt = 0; nt < NT; nt++) {
            int r = row0 + wy * 64 + mt * 16 + g;
            int cc = col0 + wx * WN + nt * 8 + tig * 2;
            if (HOUT) {
                __half2* Cm2 = reinterpret_cast<__half2*>(Cm);
                Cm2[(size_t)r * (M / 2) + cc / 2] =
                    __floats2half2_rn(acc[mt][nt][0], acc[mt][nt][1]);
                Cm2[(size_t)(r + 8) * (M / 2) + cc / 2] =
                    __floats2half2_rn(acc[mt][nt][2], acc[mt][nt][3]);
            } else {
                *reinterpret_cast<float2*>(&Cm[(size_t)r * M + cc]) =
                    make_float2(acc[mt][nt][0], acc[mt][nt][1]);
                *reinterpret_cast<float2*>(&Cm[(size_t)(r + 8) * M + cc]) =
                    make_float2(acc[mt][nt][2], acc[mt][nt][3]);
            }
        }
    }
}

// ---------------- layer-2 candidate-only aggregate ----------------
__global__ __launch_bounds__(256)
void agg2_cand_kernel(const float* __restrict__ proj, const float* __restrict__ skip,
                      const float* __restrict__ bias, const int* __restrict__ cand,
                      float* __restrict__ z) {
    const int c = blockIdx.x * 4 + (threadIdx.x >> 6);
    const int col = threadIdx.x & 63;
    const int n = cand[c];
    const int beg = g_off[n], end = g_off[n + 1];
    float acc = 0.f;
    for (int j = beg; j < end; j++)
        acc += g_alpha[j] * proj[(size_t)g_srcs[j] * 64 + col];
    z[(size_t)c * 64 + col] = acc + skip[(size_t)n * 64 + col] + bias[col];
}

// ---------------- MLP head ----------------
__global__ void mlp_kernel(const float* __restrict__ z, const int* __restrict__ cand,
                           const float* __restrict__ mW1, const float* __restrict__ mb1,
                           const float* __restrict__ mW2, const float* __restrict__ mb2,
                           const float* __restrict__ mW3, const float* __restrict__ mb3,
                           float* __restrict__ out, int out_size) {
    int c = blockIdx.x;
    int tid = threadIdx.x;
    __shared__ float sc[64];
    __shared__ float sh[256];
    if (tid < 64) sc[tid] = z[c * 64 + tid];
    __syncthreads();

    float acc = mb1[tid];
#pragma unroll 8
    for (int k = 0; k < 64; k++) acc += sc[k] * mW1[k * 256 + tid];
    float h1 = tanhf(acc);
    sh[tid] = h1;
    __syncthreads();

    acc = mb2[tid];
#pragma unroll 8
    for (int k = 0; k < 256; k++) acc += sh[k] * mW2[k * 256 + tid];
    float h2 = tanhf(acc);
    __syncthreads();

    sh[tid] = h2 * mW3[tid];
    __syncthreads();
    for (int s = 128; s; s >>= 1) {
        if (tid < s) sh[tid] += sh[tid + s];
        __syncthreads();
    }
    if (tid == 0) out[c] = sh[0] + mb3[0];
    if (out_size > NCAND && tid == 1 && (NCAND + c) < out_size) {
        out[NCAND + c] = (float)cand[c];
    }
}

// ---------------- launch ----------------
extern "C" void kernel_launch(void* const* d_in, const int* in_sizes, int n_in,
                              void* d_out, int out_size) {
    const float* fea  = (const float*)d_in[0];
    const int*   ei   = (const int*)d_in[1];
    const int*   cand = (const int*)d_in[2];
    const float* W0 = (const float*)d_in[3];
    const float* a_src0 = (const float*)d_in[4];
    const float* a_tgt0 = (const float*)d_in[5];
    const float* b0 = (const float*)d_in[6];
    const float* skip0 = (const float*)d_in[7];
    const float* W1 = (const float*)d_in[8];
    const float* a_src1 = (const float*)d_in[9];
    const float* a_tgt1 = (const float*)d_in[10];
    const float* b1 = (const float*)d_in[11];
    const float* skip1 = (const float*)d_in[12];
    const float* W2 = (const float*)d_in[13];
    const float* a_src2 = (const float*)d_in[14];
    const float* a_tgt2 = (const float*)d_in[15];
    const float* b2 = (const float*)d_in[16];
    const float* skip2 = (const float*)d_in[17];
    const float* mW1 = (const float*)d_in[18];
    const float* mb1 = (const float*)d_in[19];
    const float* mW2 = (const float*)d_in[20];
    const float* mb2 = (const float*)d_in[21];
    const float* mW3 = (const float*)d_in[22];
    const float* mb3 = (const float*)d_in[23];

    const int E = in_sizes[1] / 2;
    const int* src = ei;
    const int* tgt = ei + E;

    float *x1, *x2, *x3, *proj, *skip;
    uint32_t* wtf;
    cudaGetSymbolAddress((void**)&x1,   g_x1);
    cudaGetSymbolAddress((void**)&x2,   g_x2);
    cudaGetSymbolAddress((void**)&x3,   g_x3);
    cudaGetSymbolAddress((void**)&proj, g_proj);
    cudaGetSymbolAddress((void**)&skip, g_skip);
    cudaGetSymbolAddress((void**)&wtf,  g_wtf);

    uint32_t* W1t = wtf;
    uint32_t* S1t = wtf + 262144;
    uint32_t* W2t = wtf + 524288;
    uint32_t* S2t = wtf + 557056;

    const int SMEM_L1 = 3 * (128 * 40 + 2 * 128 * 40) * 4;
    const int SMEM_L2 = 3 * (128 * 40 + 2 * 64 * 40) * 4;
    cudaFuncSetAttribute(gemm_dualH_kernel<128, 1>,
                         cudaFuncAttributeMaxDynamicSharedMemorySize, SMEM_L1);
    cudaFuncSetAttribute(gemm_dualH_kernel<64, 0>,
                         cudaFuncAttributeMaxDynamicSharedMemorySize, SMEM_L2);

    // ---- merged setup ----
    setup1_kernel<<<1257, 256>>>(W1, skip1, W2, skip2, W0,
                                 a_src0, a_tgt0, a_src1, a_tgt1, a_src2, a_tgt2,
                                 (__half*)W1t, (__half*)S1t, (__half*)W2t, (__half*)S2t);
    setup2_kernel<<<896, 256>>>(tgt, fea);
    scan_kernel<<<1, 1024>>>();
    scatter_kernel<<<(NEDGES + 255) / 256, 256>>>(src, tgt);

    // ---- layer 0 fused agg ----
    agg0_kernel<<<NNODES, 512>>>(fea, W0, skip0, b0, (__half*)x1);

    // ---- layer 1 (agg1 also emits layer-2 scores) ----
    scores1_kernel<<<256, 256>>>((const __half2*)x1);
    alpha8_kernel<<<NNODES / 8, 256>>>();
    gemm_dualH_kernel<128, 1><<<dim3(8, NNODES / 128), 256, SMEM_L1>>>(
        (const uint32_t*)x1, W1t, S1t, proj, skip, NNODES, 256, 1024);
    agg1_kernel<<<NNODES, 256>>>((const uint2*)proj, (const uint2*)skip,
                                 (const float4*)b1, (__half*)x2);

    // ---- layer 2: dual GEMM (R15 config), candidate-only tail ----
    alpha1_cand_kernel<<<NCAND / 8, 256>>>(cand);
    gemm_dualH_kernel<64, 0><<<dim3(1, NNODES / 128), 256, SMEM_L2>>>(
        (const uint32_t*)x2, W2t, S2t, proj, skip, NNODES, 512, 64);
    agg2_cand_kernel<<<NCAND / 4, 256>>>(proj, skip, b2, cand, x3);

    // ---- MLP head ----
    mlp_kernel<<<NCAND, 256>>>(x3, cand, mW1, mb1, mW2, mb2, mW3, mb3, (float*)d_out, out_size);
}